// round 9
// baseline (speedup 1.0000x reference)
#include <cuda_runtime.h>
#include <cstdint>

#define NB 16
#define NC 64
#define NT 2048
#define KNN 3
#define NTILE 16      // NT/128
#define NPAIR 136     // NTILE*(NTILE+1)/2

// scratch (static __device__ arrays: allocation-free per harness rules)
__device__ float g_nsq[NB * NT];
__device__ float g_cs[(size_t)NB * NT * NTILE * KNN];  // candidate scores
__device__ int   g_ci[(size_t)NB * NT * NTILE * KNN];  // candidate indices

// ---------------- f32x2 helpers (sm_100+ packed fp32 FMA) --------------------------
__device__ __forceinline__ void fma2(unsigned long long& d, unsigned long long a, unsigned long long b) {
    asm("fma.rn.f32x2 %0, %1, %2, %0;" : "+l"(d) : "l"(a), "l"(b));
}

// top-3 insert with (score, index) lexicographic tie-break (== lax.top_k stability)
#define INS3(SC, SI)                                                          \
    do {                                                                      \
        float _s = (SC); int _i = (SI);                                       \
        if (_s < q2 || (_s == q2 && _i < j2)) {                               \
            q2 = _s; j2 = _i;                                                 \
            if (q2 < q1 || (q2 == q1 && j2 < j1)) {                           \
                float _t = q1; q1 = q2; q2 = _t;                              \
                int _k = j1; j1 = j2; j2 = _k;                                \
                if (q1 < q0 || (q1 == q0 && j1 < j0)) {                       \
                    _t = q0; q0 = q1; q1 = _t;                                \
                    _k = j0; j0 = j1; j1 = _k;                                \
                }                                                             \
            }                                                                 \
        }                                                                     \
    } while (0)

// ---------------- kernel 1: squared norms ------------------------------------------
__global__ void nsq_kernel(const float* __restrict__ x) {
    int gid = blockIdx.x * blockDim.x + threadIdx.x;   // 2*NB*NT threads
    int half = gid & 1;
    int t = (gid >> 1) & (NT - 1);
    int b = gid >> 12;
    const float* xp = x + ((size_t)(b * NC + half * 32)) * NT + t;
    float s = 0.f;
#pragma unroll
    for (int c = 0; c < 32; c++) {
        float v = xp[(size_t)c * NT];
        s = fmaf(v, v, s);
    }
    s += __shfl_xor_sync(0xffffffffu, s, 1);
    if (!half) g_nsq[b * NT + t] = s;
}

// ---------------- kernel 2: FFMA2 gram, deep register blocking ---------------------
// 128 threads. One block per (ti,tj) pair, tj >= ti. A tile stored VALUE-DUPLICATED
// ([c][2t]=[c][2t+1]=x) so a-operands are direct LDS.64 pairs (no dup MOVs).
// Thread tile: 8 rows (strided 16: r = ty+16i) x 16 cols (8 pairs: 2(tx+8q)).
// smem traffic 1.5 B/FMA-pair; issue 80 slots per c-iter vs >=128 fma-pipe cycles.
// Score buffer stride 144 => conflict-free STS.64 dump + both scans.
extern __shared__ float smem[];

// float offsets within dynamic smem
#define SM_AT2  0          // [64][288] dup'd A tile; overlaid by score [128][144]
#define SM_BS   18432      // [64][136] B tile
#define SM_NSQR 27136
#define SM_NSQC 27264
#define GRAM_SMEM_BYTES (27392 * 4)   // 109568 B -> 2 blocks/SM

__global__ __launch_bounds__(128) void gram_kernel(const float* __restrict__ x) {
    const int tid = threadIdx.x;
    const int tx  = tid & 7;    // col-pair group: pairs tx + 8q
    const int ty  = tid >> 3;   // row group 0..15: rows ty + 16*i
    const int b   = blockIdx.y;

    // closed-form upper-triangle decode: p -> (ti, tj), tj >= ti
    const int p = blockIdx.x;
    int ti = (int)(NTILE + 0.5f - sqrtf((NTILE + 0.5f) * (NTILE + 0.5f) - 2.0f * p));
    int off = ti * NTILE - (ti * (ti - 1)) / 2;
    if (p < off)                    { ti--; off = ti * NTILE - (ti * (ti - 1)) / 2; }
    else if (p >= off + NTILE - ti) { ti++; off = ti * NTILE - (ti * (ti - 1)) / 2; }
    const int tj = ti + (p - off);
    const int t0 = ti * 128, s0 = tj * 128;
    const bool diag = (ti == tj);

    const float4* xb4 = (const float4*)(x + (size_t)b * NC * NT);

    // ---- load: A duplicated ([c][288]), B plain ([c][136]) ----
    for (int i = tid; i < 2048; i += 128) {
        int c = i >> 5, t4 = i & 31;
        float4 g = xb4[c * (NT / 4) + (t0 >> 2) + t4];
        *(float4*)&smem[SM_AT2 + c * 288 + 8 * t4]     = make_float4(g.x, g.x, g.y, g.y);
        *(float4*)&smem[SM_AT2 + c * 288 + 8 * t4 + 4] = make_float4(g.z, g.z, g.w, g.w);
    }
    for (int i = tid; i < 2048; i += 128) {
        int c = i >> 5, t4 = i & 31;
        *(float4*)&smem[SM_BS + c * 136 + 4 * t4] = xb4[c * (NT / 4) + (s0 >> 2) + t4];
    }
    smem[SM_NSQR + tid] = g_nsq[b * NT + t0 + tid];
    smem[SM_NSQC + tid] = g_nsq[b * NT + s0 + tid];
    __syncthreads();

    // ---- mainloop: 64 FFMA2 per c-iter per thread, zero MOV overhead ----
    unsigned long long acc[8][8];
#pragma unroll
    for (int i = 0; i < 8; i++)
#pragma unroll
        for (int q = 0; q < 8; q++) acc[i][q] = 0ull;

#pragma unroll 4
    for (int c = 0; c < 64; c++) {
        unsigned long long av[8], bv[8];
#pragma unroll
        for (int i = 0; i < 8; i++)   // banks (ty)%16 distinct, 8-way broadcast
            av[i] = *(const unsigned long long*)&smem[SM_AT2 + c * 288 + 2 * (ty + 16 * i)];
#pragma unroll
        for (int q = 0; q < 8; q++)   // banks (tx+8q) distinct, 4-way broadcast
            bv[q] = *(const unsigned long long*)&smem[SM_BS + c * 136 + 2 * (tx + 8 * q)];
#pragma unroll
        for (int i = 0; i < 8; i++)
#pragma unroll
            for (int q = 0; q < 8; q++)
                fma2(acc[i][q], av[i], bv[q]);
    }
    __syncthreads();   // At2 reads done before score overlays it

    // ---- dump to score[128][144]: STS.64 bank = (8*ty + tx + 8q) mod 16: phase-distinct ----
    float* score = smem;
#pragma unroll
    for (int i = 0; i < 8; i++) {
        int r = ty + 16 * i;
#pragma unroll
        for (int q = 0; q < 8; q++)
            *(unsigned long long*)&score[r * 144 + 2 * (tx + 8 * q)] = acc[i][q];
    }
    __syncthreads();

    const float* nsqR = smem + SM_NSQR;
    const float* nsqC = smem + SM_NSQC;

    // ---- row scan: thread tid = row t0+tid, skewed (17 odd => bank permutation) ----
    {
        float q0 = 3.4e38f, q1 = 3.4e38f, q2 = 3.4e38f;
        int   j0 = 0x7fffffff, j1 = 0x7fffffff, j2 = 0x7fffffff;
        const float* rowp = &score[tid * 144];
        for (int i = 0; i < 128; i++) {
            int jj = (i + tid) & 127;
            float sc = fmaf(-2.f, rowp[jj], nsqC[jj]);
            INS3(sc, s0 + jj);
        }
        size_t base = ((size_t)(b * NT + t0 + tid) * NTILE + tj) * KNN;
        g_cs[base + 0] = q0; g_ci[base + 0] = j0;
        g_cs[base + 1] = q1; g_ci[base + 1] = j1;
        g_cs[base + 2] = q2; g_ci[base + 2] = j2;
    }
    // ---- column scan: thread tid = col s0+tid; fixed col => lanes hit distinct banks ----
    if (!diag) {
        float q0 = 3.4e38f, q1 = 3.4e38f, q2 = 3.4e38f;
        int   j0 = 0x7fffffff, j1 = 0x7fffffff, j2 = 0x7fffffff;
        for (int jj = 0; jj < 128; jj++) {
            float sc = fmaf(-2.f, score[jj * 144 + tid], nsqR[jj]);
            INS3(sc, t0 + jj);
        }
        size_t base = ((size_t)(b * NT + s0 + tid) * NTILE + ti) * KNN;
        g_cs[base + 0] = q0; g_ci[base + 0] = j0;
        g_cs[base + 1] = q1; g_ci[base + 1] = j1;
        g_cs[base + 2] = q2; g_ci[base + 2] = j2;
    }
}

// ---------------- kernel 3: candidate merge + gather + conv ------------------------
// out[b,o,t] = bias[o] + sum_j W[o*192+j] * x[b, j/3, idx[b,t,j%3]]
__global__ __launch_bounds__(256) void conv_kernel(const float* __restrict__ x,
                                                   const float* __restrict__ W,
                                                   const float* __restrict__ bias,
                                                   float* __restrict__ out) {
    const int b  = blockIdx.y;
    const int t0 = blockIdx.x * 128;
    float* Ws   = smem;                                 // [192][64] transposed
    float* ps   = smem + 192 * 64;                      // [64][128] gathered chunk
    int*   sidx = (int*)(smem + 192 * 64 + 64 * 128);   // [128*3]

    const int tid = threadIdx.x;
    for (int i = tid; i < 192 * 64; i += 256) {
        int j = i >> 6, o = i & 63;
        Ws[i] = W[o * 192 + j];
    }
    // merge this block's 128 rows: 16 slots x 3 candidates -> final top-3
    if (tid < 128) {
        size_t cb = (size_t)(b * NT + t0 + tid) * (NTILE * KNN);
        float q0 = 3.4e38f, q1 = 3.4e38f, q2 = 3.4e38f;
        int   j0 = 0x7fffffff, j1 = 0x7fffffff, j2 = 0x7fffffff;
#pragma unroll 8
        for (int e = 0; e < NTILE * KNN; e++) {
            float sc = g_cs[cb + e];
            int   si = g_ci[cb + e];
            INS3(sc, si);
        }
        sidx[tid * KNN + 0] = j0;
        sidx[tid * KNN + 1] = j1;
        sidx[tid * KNN + 2] = j2;
    }

    const int to = tid & 15;   // o-group: o = to*4 .. +3
    const int tt = tid >> 4;   // t-group: t = tt*8 .. +7
    float acc[4][8];
#pragma unroll
    for (int r = 0; r < 4; r++)
#pragma unroll
        for (int e = 0; e < 8; e++) acc[r][e] = 0.f;

    const float* xb = x + (size_t)b * NC * NT;

    for (int jc = 0; jc < 3; jc++) {
        __syncthreads();  // Ws/sidx ready (first), ps free (later)
        for (int i = tid; i < 64 * 128; i += 256) {
            int jj = i >> 7, tl = i & 127;
            int j  = jc * 64 + jj;
            int ch = j / 3;
            int kk = j - ch * 3;
            ps[i] = xb[(size_t)ch * NT + sidx[tl * KNN + kk]];  // L2-resident gather
        }
        __syncthreads();
#pragma unroll 8
        for (int jj = 0; jj < 64; jj++) {
            float4 w4 = *(const float4*)&Ws[(jc * 64 + jj) * 64 + to * 4];
            float4 p0 = *(const float4*)&ps[jj * 128 + tt * 8];
            float4 p1 = *(const float4*)&ps[jj * 128 + tt * 8 + 4];
            float pv[8] = {p0.x, p0.y, p0.z, p0.w, p1.x, p1.y, p1.z, p1.w};
            float wv[4] = {w4.x, w4.y, w4.z, w4.w};
#pragma unroll
            for (int r = 0; r < 4; r++)
#pragma unroll
                for (int e = 0; e < 8; e++)
                    acc[r][e] = fmaf(wv[r], pv[e], acc[r][e]);
        }
    }

#pragma unroll
    for (int r = 0; r < 4; r++) {
        int o = to * 4 + r;
        float bo = __ldg(&bias[o]);
        float* op = out + ((size_t)(b * NC + o)) * NT + t0 + tt * 8;
#pragma unroll
        for (int e = 0; e < 8; e++) op[e] = acc[r][e] + bo;
    }
}

// ---------------- launch -----------------------------------------------------------
extern "C" void kernel_launch(void* const* d_in, const int* in_sizes, int n_in,
                              void* d_out, int out_size) {
    const float* x    = (const float*)d_in[0];
    const float* W    = (const float*)d_in[1];
    const float* bias = (const float*)d_in[2];
    float* out        = (float*)d_out;

    const int conv_smem = (192 * 64 + 64 * 128 + 128 * KNN) * 4;          // 83456 B
    cudaFuncSetAttribute(gram_kernel, cudaFuncAttributeMaxDynamicSharedMemorySize, GRAM_SMEM_BYTES);
    cudaFuncSetAttribute(conv_kernel, cudaFuncAttributeMaxDynamicSharedMemorySize, conv_smem);

    nsq_kernel<<<(2 * NB * NT) / 256, 256>>>(x);
    gram_kernel<<<dim3(NPAIR, NB), 128, GRAM_SMEM_BYTES>>>(x);
    conv_kernel<<<dim3(NT / 128, NB), 256, conv_smem>>>(x, W, bias, out);
}

// round 10
// speedup vs baseline: 2.0747x; 2.0747x over previous
#include <cuda_runtime.h>
#include <cstdint>

#define NB 16
#define NC 64
#define NT 2048
#define KNN 3
#define NTILE 16      // NT/128
#define NPAIR 136     // NTILE*(NTILE+1)/2

// scratch (static __device__ arrays: allocation-free per harness rules)
__device__ float g_nsq[NB * NT];
__device__ float g_cs[(size_t)NB * NT * NTILE * KNN];  // candidate scores
__device__ int   g_ci[(size_t)NB * NT * NTILE * KNN];  // candidate indices

// ---------------- f32x2 helpers (sm_100+ packed fp32 FMA) --------------------------
__device__ __forceinline__ void fma2(unsigned long long& d, unsigned long long a, unsigned long long b) {
    asm("fma.rn.f32x2 %0, %1, %2, %0;" : "+l"(d) : "l"(a), "l"(b));
}

// top-3 insert with (score, index) lexicographic tie-break (== lax.top_k stability)
#define INS3(SC, SI)                                                          \
    do {                                                                      \
        float _s = (SC); int _i = (SI);                                       \
        if (_s < q2 || (_s == q2 && _i < j2)) {                               \
            q2 = _s; j2 = _i;                                                 \
            if (q2 < q1 || (q2 == q1 && j2 < j1)) {                           \
                float _t = q1; q1 = q2; q2 = _t;                              \
                int _k = j1; j1 = j2; j2 = _k;                                \
                if (q1 < q0 || (q1 == q0 && j1 < j0)) {                       \
                    _t = q0; q0 = q1; q1 = _t;                                \
                    _k = j0; j0 = j1; j1 = _k;                                \
                }                                                             \
            }                                                                 \
        }                                                                     \
    } while (0)

// ---------------- kernel 1: squared norms ------------------------------------------
__global__ void nsq_kernel(const float* __restrict__ x) {
    int gid = blockIdx.x * blockDim.x + threadIdx.x;   // 2*NB*NT threads
    int half = gid & 1;
    int t = (gid >> 1) & (NT - 1);
    int b = gid >> 12;
    const float* xp = x + ((size_t)(b * NC + half * 32)) * NT + t;
    float s = 0.f;
#pragma unroll
    for (int c = 0; c < 32; c++) {
        float v = xp[(size_t)c * NT];
        s = fmaf(v, v, s);
    }
    s += __shfl_xor_sync(0xffffffffu, s, 1);
    if (!half) g_nsq[b * NT + t] = s;
}

// ---------------- kernel 2: symmetric gram tile + bidirectional top-3 --------------
// R4 structure (256 threads, 4 rows x 16 cols per thread) with a value-duplicated
// A tile: [c][2t]=[c][2t+1]=x (stride 264), so a-operands are direct LDS.64 pairs,
// eliminating the LDS.128 + dup-MOV chain of R4. FMA order (c ascending) is
// unchanged => bit-identical results. Score overlay stride 132 as in R4.
extern __shared__ float smem[];

// float offsets within dynamic smem
#define SM_AT2  0          // [64][264] dup'd A tile; overlaid by score [128][132] = 16896 floats
#define SM_BS   16896      // [64][136] B tile
#define SM_NSQR 25600
#define SM_NSQC 25728
#define GRAM_SMEM_BYTES (25856 * 4)   // 103424 B -> 2 blocks/SM

__global__ __launch_bounds__(256) void gram_kernel(const float* __restrict__ x) {
    const int tid = threadIdx.x;
    const int tx  = tid & 7;    // col-pair group: pairs tx + 8q
    const int ty  = tid >> 3;   // row group 0..31: rows ty*4 .. +3
    const int b   = blockIdx.y;

    // closed-form upper-triangle decode: p -> (ti, tj), tj >= ti
    const int p = blockIdx.x;
    int ti = (int)(NTILE + 0.5f - sqrtf((NTILE + 0.5f) * (NTILE + 0.5f) - 2.0f * p));
    int off = ti * NTILE - (ti * (ti - 1)) / 2;
    if (p < off)                    { ti--; off = ti * NTILE - (ti * (ti - 1)) / 2; }
    else if (p >= off + NTILE - ti) { ti++; off = ti * NTILE - (ti * (ti - 1)) / 2; }
    const int tj = ti + (p - off);
    const int t0 = ti * 128, s0 = tj * 128;
    const bool diag = (ti == tj);

    const float4* xb4 = (const float4*)(x + (size_t)b * NC * NT);

    // ---- load: A duplicated ([c][264]), B plain ([c][136]) ----
    for (int i = tid; i < 2048; i += 256) {
        int c = i >> 5, t4 = i & 31;
        float4 g = xb4[c * (NT / 4) + (t0 >> 2) + t4];
        *(float4*)&smem[SM_AT2 + c * 264 + 8 * t4]     = make_float4(g.x, g.x, g.y, g.y);
        *(float4*)&smem[SM_AT2 + c * 264 + 8 * t4 + 4] = make_float4(g.z, g.z, g.w, g.w);
    }
    for (int i = tid; i < 2048; i += 256) {
        int c = i >> 5, t4 = i & 31;
        *(float4*)&smem[SM_BS + c * 136 + 4 * t4] = xb4[c * (NT / 4) + (s0 >> 2) + t4];
    }
    if (tid < 128) smem[SM_NSQR + tid] = g_nsq[b * NT + t0 + tid];
    else           smem[SM_NSQC + tid - 128] = g_nsq[b * NT + s0 + tid - 128];
    __syncthreads();

    // ---- mainloop: 12 LDS.64 + 32 FFMA2 per c-iter, zero MOV overhead ----
    unsigned long long acc[4][8];
#pragma unroll
    for (int r = 0; r < 4; r++)
#pragma unroll
        for (int q = 0; q < 8; q++) acc[r][q] = 0ull;

#pragma unroll 8
    for (int c = 0; c < 64; c++) {
        unsigned long long av[4], bv[8];
#pragma unroll
        for (int i = 0; i < 4; i++)   // 4 distinct addrs/warp, 8-way broadcast
            av[i] = *(const unsigned long long*)&smem[SM_AT2 + c * 264 + 2 * (ty * 4 + i)];
#pragma unroll
        for (int q = 0; q < 8; q++)   // 8 distinct addrs/warp, 4-way broadcast
            bv[q] = *(const unsigned long long*)&smem[SM_BS + c * 136 + 2 * (tx + 8 * q)];
#pragma unroll
        for (int q = 0; q < 8; q++) {
            fma2(acc[0][q], av[0], bv[q]);
            fma2(acc[1][q], av[1], bv[q]);
            fma2(acc[2][q], av[2], bv[q]);
            fma2(acc[3][q], av[3], bv[q]);
        }
    }
    __syncthreads();   // At2/Bs reads done before score overlays At2

    // ---- dump dot tile to score[128][132] ----
    float* score = smem;
#pragma unroll
    for (int r = 0; r < 4; r++)
#pragma unroll
        for (int q = 0; q < 8; q++)
            *(unsigned long long*)&score[(ty * 4 + r) * 132 + 2 * (tx + 8 * q)] = acc[r][q];
    __syncthreads();

    const float* nsqR = smem + SM_NSQR;
    const float* nsqC = smem + SM_NSQC;

    // row-side (tid<128) and column-side (tid>=128) scans run concurrently
    if (tid < 128) {
        float q0 = 3.4e38f, q1 = 3.4e38f, q2 = 3.4e38f;
        int   j0 = 0x7fffffff, j1 = 0x7fffffff, j2 = 0x7fffffff;
        const float* rowp = &score[tid * 132];
#pragma unroll 4
        for (int i = 0; i < 128; i++) {
            int jj = (i + tid) & 127;                   // skew: conflict-free (pad 132)
            float sc = fmaf(-2.f, rowp[jj], nsqC[jj]);
            INS3(sc, s0 + jj);
        }
        size_t base = ((size_t)(b * NT + t0 + tid) * NTILE + tj) * KNN;
        g_cs[base + 0] = q0; g_ci[base + 0] = j0;
        g_cs[base + 1] = q1; g_ci[base + 1] = j1;
        g_cs[base + 2] = q2; g_ci[base + 2] = j2;
    } else if (!diag) {
        int cc = tid - 128;
        float q0 = 3.4e38f, q1 = 3.4e38f, q2 = 3.4e38f;
        int   j0 = 0x7fffffff, j1 = 0x7fffffff, j2 = 0x7fffffff;
#pragma unroll 4
        for (int i = 0; i < 128; i++) {
            int jj = (i + cc) & 127;
            float sc = fmaf(-2.f, score[jj * 132 + cc], nsqR[jj]);
            INS3(sc, t0 + jj);
        }
        size_t base = ((size_t)(b * NT + s0 + cc) * NTILE + ti) * KNN;
        g_cs[base + 0] = q0; g_ci[base + 0] = j0;
        g_cs[base + 1] = q1; g_ci[base + 1] = j1;
        g_cs[base + 2] = q2; g_ci[base + 2] = j2;
    }
}

// ---------------- kernel 3: candidate merge + gather + conv ------------------------
// out[b,o,t] = bias[o] + sum_j W[o*192+j] * x[b, j/3, idx[b,t,j%3]]
__global__ __launch_bounds__(256) void conv_kernel(const float* __restrict__ x,
                                                   const float* __restrict__ W,
                                                   const float* __restrict__ bias,
                                                   float* __restrict__ out) {
    const int b  = blockIdx.y;
    const int t0 = blockIdx.x * 128;
    float* Ws   = smem;                                 // [192][64] transposed
    float* ps   = smem + 192 * 64;                      // [64][128] gathered chunk
    int*   sidx = (int*)(smem + 192 * 64 + 64 * 128);   // [128*3]

    const int tid = threadIdx.x;
    for (int i = tid; i < 192 * 64; i += 256) {
        int j = i >> 6, o = i & 63;
        Ws[i] = W[o * 192 + j];
    }
    // merge this block's 128 rows: 16 slots x 3 candidates -> final top-3
    if (tid < 128) {
        size_t cb = (size_t)(b * NT + t0 + tid) * (NTILE * KNN);
        float q0 = 3.4e38f, q1 = 3.4e38f, q2 = 3.4e38f;
        int   j0 = 0x7fffffff, j1 = 0x7fffffff, j2 = 0x7fffffff;
#pragma unroll 8
        for (int e = 0; e < NTILE * KNN; e++) {
            float sc = g_cs[cb + e];
            int   si = g_ci[cb + e];
            INS3(sc, si);
        }
        sidx[tid * KNN + 0] = j0;
        sidx[tid * KNN + 1] = j1;
        sidx[tid * KNN + 2] = j2;
    }

    const int to = tid & 15;   // o-group: o = to*4 .. +3
    const int tt = tid >> 4;   // t-group: t = tt*8 .. +7
    float acc[4][8];
#pragma unroll
    for (int r = 0; r < 4; r++)
#pragma unroll
        for (int e = 0; e < 8; e++) acc[r][e] = 0.f;

    const float* xb = x + (size_t)b * NC * NT;

    for (int jc = 0; jc < 3; jc++) {
        __syncthreads();  // Ws/sidx ready (first), ps free (later)
        for (int i = tid; i < 64 * 128; i += 256) {
            int jj = i >> 7, tl = i & 127;
            int j  = jc * 64 + jj;
            int ch = j / 3;
            int kk = j - ch * 3;
            ps[i] = xb[(size_t)ch * NT + sidx[tl * KNN + kk]];  // L2-resident gather
        }
        __syncthreads();
#pragma unroll 8
        for (int jj = 0; jj < 64; jj++) {
            float4 w4 = *(const float4*)&Ws[(jc * 64 + jj) * 64 + to * 4];
            float4 p0 = *(const float4*)&ps[jj * 128 + tt * 8];
            float4 p1 = *(const float4*)&ps[jj * 128 + tt * 8 + 4];
            float pv[8] = {p0.x, p0.y, p0.z, p0.w, p1.x, p1.y, p1.z, p1.w};
            float wv[4] = {w4.x, w4.y, w4.z, w4.w};
#pragma unroll
            for (int r = 0; r < 4; r++)
#pragma unroll
                for (int e = 0; e < 8; e++)
                    acc[r][e] = fmaf(wv[r], pv[e], acc[r][e]);
        }
    }

#pragma unroll
    for (int r = 0; r < 4; r++) {
        int o = to * 4 + r;
        float bo = __ldg(&bias[o]);
        float* op = out + ((size_t)(b * NC + o)) * NT + t0 + tt * 8;
#pragma unroll
        for (int e = 0; e < 8; e++) op[e] = acc[r][e] + bo;
    }
}

// ---------------- launch -----------------------------------------------------------
extern "C" void kernel_launch(void* const* d_in, const int* in_sizes, int n_in,
                              void* d_out, int out_size) {
    const float* x    = (const float*)d_in[0];
    const float* W    = (const float*)d_in[1];
    const float* bias = (const float*)d_in[2];
    float* out        = (float*)d_out;

    const int conv_smem = (192 * 64 + 64 * 128 + 128 * KNN) * 4;          // 83456 B
    cudaFuncSetAttribute(gram_kernel, cudaFuncAttributeMaxDynamicSharedMemorySize, GRAM_SMEM_BYTES);
    cudaFuncSetAttribute(conv_kernel, cudaFuncAttributeMaxDynamicSharedMemorySize, conv_smem);

    nsq_kernel<<<(2 * NB * NT) / 256, 256>>>(x);
    gram_kernel<<<dim3(NPAIR, NB), 256, GRAM_SMEM_BYTES>>>(x);
    conv_kernel<<<dim3(NT / 128, NB), 256, conv_smem>>>(x, W, bias, out);
}

// round 11
// speedup vs baseline: 2.3365x; 1.1262x over previous
#include <cuda_runtime.h>
#include <cstdint>

#define NB 16
#define NC 64
#define NT 2048
#define KNN 3
#define NTILE 16      // NT/128
#define NPAIR 136     // NTILE*(NTILE+1)/2

// scratch (static __device__ arrays: allocation-free per harness rules)
__device__ float g_cs[(size_t)NB * NT * NTILE * KNN];  // candidate scores
__device__ int   g_ci[(size_t)NB * NT * NTILE * KNN];  // candidate indices

// ---------------- f32x2 helpers (sm_100+ packed fp32 FMA) --------------------------
__device__ __forceinline__ unsigned long long dup2(float v) {
    unsigned long long r;
    asm("mov.b64 %0, {%1, %1};" : "=l"(r) : "f"(v));
    return r;
}
__device__ __forceinline__ void fma2(unsigned long long& d, unsigned long long a, unsigned long long b) {
    asm("fma.rn.f32x2 %0, %1, %2, %0;" : "+l"(d) : "l"(a), "l"(b));
}
__device__ __forceinline__ void unpack2(unsigned long long v, float& lo, float& hi) {
    asm("mov.b64 {%0, %1}, %2;" : "=f"(lo), "=f"(hi) : "l"(v));
}
__device__ __forceinline__ uint32_t smem_u32(const void* p) {
    uint32_t a;
    asm("{ .reg .u64 t; cvta.to.shared.u64 t, %1; cvt.u32.u64 %0, t; }" : "=r"(a) : "l"(p));
    return a;
}
__device__ __forceinline__ void cp_async16(uint32_t dst, const void* src) {
    asm volatile("cp.async.ca.shared.global [%0], [%1], 16;" :: "r"(dst), "l"(src) : "memory");
}

// top-3 insert with (score, index) lexicographic tie-break (== lax.top_k stability)
#define INS3(SC, SI)                                                          \
    do {                                                                      \
        float _s = (SC); int _i = (SI);                                       \
        if (_s < q2 || (_s == q2 && _i < j2)) {                               \
            q2 = _s; j2 = _i;                                                 \
            if (q2 < q1 || (q2 == q1 && j2 < j1)) {                           \
                float _t = q1; q1 = q2; q2 = _t;                              \
                int _k = j1; j1 = j2; j2 = _k;                                \
                if (q1 < q0 || (q1 == q0 && j1 < j0)) {                       \
                    _t = q0; q0 = q1; q1 = _t;                                \
                    _k = j0; j0 = j1; j1 = _k;                                \
                }                                                             \
            }                                                                 \
        }                                                                     \
    } while (0)

// ---------------- kernel 1: gram + nsq + bidirectional top-3 -----------------------
// R4 structure exactly (256 thr, 4 rows x 16 cols/thread, 68608 B smem, 3 blk/SM)
// plus: cp.async tile staging, in-kernel nsq (bit-identical two-half sums), and
// float2 row scan. One block per (ti,tj) pair, tj >= ti.
extern __shared__ float smem[];

__global__ __launch_bounds__(256) void gram_kernel(const float* __restrict__ x) {
    float* At   = smem;                 // [64][128]   (phase 1)
    float* Bs   = smem + 64 * 128;      // [64][128]   (phase 1)
    float* score = smem;                // [128][132]  (phase 2 overlay)
    float* nsqR = smem + 128 * 132;     // [128]
    float* nsqC = nsqR + 128;           // [128]

    const int tid = threadIdx.x;
    const int tx  = tid & 7;    // col-pair group: pairs tx + 8q
    const int ty  = tid >> 3;   // row group: rows ty*4 .. +3
    const int b   = blockIdx.y;

    // closed-form upper-triangle decode: p -> (ti, tj), tj >= ti
    const int p = blockIdx.x;
    int ti = (int)(NTILE + 0.5f - sqrtf((NTILE + 0.5f) * (NTILE + 0.5f) - 2.0f * p));
    int off = ti * NTILE - (ti * (ti - 1)) / 2;
    if (p < off)                    { ti--; off = ti * NTILE - (ti * (ti - 1)) / 2; }
    else if (p >= off + NTILE - ti) { ti++; off = ti * NTILE - (ti * (ti - 1)) / 2; }
    const int tj = ti + (p - off);
    const int t0 = ti * 128, s0 = tj * 128;
    const bool diag = (ti == tj);

    const float4* xb4 = (const float4*)(x + (size_t)b * NC * NT);
    const uint32_t atb = smem_u32(At);
    const uint32_t bsb = smem_u32(Bs);

    // ---- stage tiles via cp.async (8 x 16B per thread per tile) ----
#pragma unroll
    for (int it = 0; it < 8; it++) {
        int i = tid + it * 256;
        int c = i >> 5, t4 = i & 31;
        cp_async16(atb + (c * 128 + 4 * t4) * 4, &xb4[c * (NT / 4) + (t0 >> 2) + t4]);
    }
#pragma unroll
    for (int it = 0; it < 8; it++) {
        int i = tid + it * 256;
        int c = i >> 5, t4 = i & 31;
        cp_async16(bsb + (c * 128 + 4 * t4) * 4, &xb4[c * (NT / 4) + (s0 >> 2) + t4]);
    }
    asm volatile("cp.async.commit_group;");
    asm volatile("cp.async.wait_group 0;" ::: "memory");
    __syncthreads();

    // ---- in-kernel nsq (bit-identical to old nsq_kernel: two half-sums) ----
    {
        const float* src = (tid < 128) ? At : Bs;
        float* dst       = (tid < 128) ? nsqR : nsqC;
        int t = tid & 127;
        float s0h = 0.f, s1h = 0.f;
#pragma unroll
        for (int c = 0; c < 32; c++) {
            float v = src[c * 128 + t];
            s0h = fmaf(v, v, s0h);
        }
#pragma unroll
        for (int c = 32; c < 64; c++) {
            float v = src[c * 128 + t];
            s1h = fmaf(v, v, s1h);
        }
        dst[t] = s0h + s1h;
    }
    // (no barrier needed here: nsq consumed only after the post-mainloop barrier)

    // ---- mainloop (R4-exact) ----
    unsigned long long acc[4][8];
#pragma unroll
    for (int r = 0; r < 4; r++)
#pragma unroll
        for (int q = 0; q < 8; q++) acc[r][q] = 0ull;

#pragma unroll 8
    for (int c = 0; c < 64; c++) {
        float4 a4 = *(const float4*)&At[c * 128 + ty * 4];
        unsigned long long ad0 = dup2(a4.x), ad1 = dup2(a4.y);
        unsigned long long ad2 = dup2(a4.z), ad3 = dup2(a4.w);
        const unsigned long long* bq = (const unsigned long long*)&Bs[c * 128];
        unsigned long long bv[8];
#pragma unroll
        for (int q = 0; q < 8; q++) bv[q] = bq[tx + 8 * q];   // 4-way broadcast
#pragma unroll
        for (int q = 0; q < 8; q++) {
            fma2(acc[0][q], ad0, bv[q]);
            fma2(acc[1][q], ad1, bv[q]);
            fma2(acc[2][q], ad2, bv[q]);
            fma2(acc[3][q], ad3, bv[q]);
        }
    }
    __syncthreads();   // At/Bs reads + nsq writes done before score overlays tiles

    // ---- dump dot tile: STS.64, conflict-free (132 = 4 mod 16 padding) ----
#pragma unroll
    for (int r = 0; r < 4; r++)
#pragma unroll
        for (int q = 0; q < 8; q++)
            *(unsigned long long*)&score[(ty * 4 + r) * 132 + 2 * (tx + 8 * q)] = acc[r][q];
    __syncthreads();

    if (tid < 128) {
        // row scan (float2: 64 skewed pair-iterations, conflict-free by half-warp phase)
        float q0 = 3.4e38f, q1 = 3.4e38f, q2 = 3.4e38f;
        int   j0 = 0x7fffffff, j1 = 0x7fffffff, j2 = 0x7fffffff;
        const float2* rowp2 = (const float2*)&score[tid * 132];
        const float2* nsc2  = (const float2*)nsqC;
#pragma unroll 4
        for (int i = 0; i < 64; i++) {
            int pj = (i + tid) & 63;
            float2 d2 = rowp2[pj];
            float2 n2 = nsc2[pj];
            float scl = fmaf(-2.f, d2.x, n2.x);
            float sch = fmaf(-2.f, d2.y, n2.y);
            INS3(scl, s0 + 2 * pj);
            INS3(sch, s0 + 2 * pj + 1);
        }
        size_t base = ((size_t)(b * NT + t0 + tid) * NTILE + tj) * KNN;
        g_cs[base + 0] = q0; g_ci[base + 0] = j0;
        g_cs[base + 1] = q1; g_ci[base + 1] = j1;
        g_cs[base + 2] = q2; g_ci[base + 2] = j2;
    } else if (!diag) {
        // column scan: candidates for row s0+cc over t in [t0, t0+128)
        int cc = tid - 128;
        float q0 = 3.4e38f, q1 = 3.4e38f, q2 = 3.4e38f;
        int   j0 = 0x7fffffff, j1 = 0x7fffffff, j2 = 0x7fffffff;
#pragma unroll 4
        for (int i = 0; i < 128; i++) {
            int jj = (i + cc) & 127;
            float sc = fmaf(-2.f, score[jj * 132 + cc], nsqR[jj]);
            INS3(sc, t0 + jj);
        }
        size_t base = ((size_t)(b * NT + s0 + cc) * NTILE + ti) * KNN;
        g_cs[base + 0] = q0; g_ci[base + 0] = j0;
        g_cs[base + 1] = q1; g_ci[base + 1] = j1;
        g_cs[base + 2] = q2; g_ci[base + 2] = j2;
    }
}

// ---------------- kernel 2: candidate merge + gather + conv (f32x2 inner) ----------
// out[b,o,t] = bias[o] + sum_j W[o*192+j] * x[b, j/3, idx[b,t,j%3]]
__global__ __launch_bounds__(256) void conv_kernel(const float* __restrict__ x,
                                                   const float* __restrict__ W,
                                                   const float* __restrict__ bias,
                                                   float* __restrict__ out) {
    const int b  = blockIdx.y;
    const int t0 = blockIdx.x * 128;
    float* Ws   = smem;                                 // [192][64] transposed
    float* ps   = smem + 192 * 64;                      // [64][128] gathered chunk
    int*   sidx = (int*)(smem + 192 * 64 + 64 * 128);   // [128*3]

    const int tid = threadIdx.x;
    for (int i = tid; i < 192 * 64; i += 256) {
        int j = i >> 6, o = i & 63;
        Ws[i] = W[o * 192 + j];
    }
    // merge this block's 128 rows: 16 slots x 3 candidates -> final top-3
    if (tid < 128) {
        size_t cb = (size_t)(b * NT + t0 + tid) * (NTILE * KNN);
        float q0 = 3.4e38f, q1 = 3.4e38f, q2 = 3.4e38f;
        int   j0 = 0x7fffffff, j1 = 0x7fffffff, j2 = 0x7fffffff;
#pragma unroll 8
        for (int e = 0; e < NTILE * KNN; e++) {
            float sc = g_cs[cb + e];
            int   si = g_ci[cb + e];
            INS3(sc, si);
        }
        sidx[tid * KNN + 0] = j0;
        sidx[tid * KNN + 1] = j1;
        sidx[tid * KNN + 2] = j2;
    }

    const int to = tid & 15;   // o-group: o = to*4 .. +3
    const int tt = tid >> 4;   // t-group: t = tt*8 .. +7 (4 pairs)
    unsigned long long acc2[4][4];
#pragma unroll
    for (int r = 0; r < 4; r++)
#pragma unroll
        for (int e = 0; e < 4; e++) acc2[r][e] = 0ull;

    const float* xb = x + (size_t)b * NC * NT;

    for (int jc = 0; jc < 3; jc++) {
        __syncthreads();  // Ws/sidx ready (first), ps free (later)
        for (int i = tid; i < 64 * 128; i += 256) {
            int jj = i >> 7, tl = i & 127;
            int j  = jc * 64 + jj;
            int ch = j / 3;
            int kk = j - ch * 3;
            ps[i] = xb[(size_t)ch * NT + sidx[tl * KNN + kk]];  // L2-resident gather
        }
        __syncthreads();
#pragma unroll 8
        for (int jj = 0; jj < 64; jj++) {
            float4 w4 = *(const float4*)&Ws[(jc * 64 + jj) * 64 + to * 4];
            unsigned long long wd0 = dup2(w4.x), wd1 = dup2(w4.y);
            unsigned long long wd2 = dup2(w4.z), wd3 = dup2(w4.w);
            const unsigned long long* pr = (const unsigned long long*)&ps[jj * 128 + tt * 8];
#pragma unroll
            for (int e = 0; e < 4; e++) {
                unsigned long long pv = pr[e];
                fma2(acc2[0][e], wd0, pv);
                fma2(acc2[1][e], wd1, pv);
                fma2(acc2[2][e], wd2, pv);
                fma2(acc2[3][e], wd3, pv);
            }
        }
    }

#pragma unroll
    for (int r = 0; r < 4; r++) {
        int o = to * 4 + r;
        float bo = __ldg(&bias[o]);
        float* op = out + ((size_t)(b * NC + o)) * NT + t0 + tt * 8;
#pragma unroll
        for (int e = 0; e < 4; e++) {
            float lo, hi;
            unpack2(acc2[r][e], lo, hi);
            *(float2*)&op[2 * e] = make_float2(lo + bo, hi + bo);
        }
    }
}

// ---------------- launch -----------------------------------------------------------
extern "C" void kernel_launch(void* const* d_in, const int* in_sizes, int n_in,
                              void* d_out, int out_size) {
    const float* x    = (const float*)d_in[0];
    const float* W    = (const float*)d_in[1];
    const float* bias = (const float*)d_in[2];
    float* out        = (float*)d_out;

    const int gram_smem = (128 * 132 + 256) * 4;                          // 68608 B
    const int conv_smem = (192 * 64 + 64 * 128 + 128 * KNN) * 4;          // 83456 B
    cudaFuncSetAttribute(gram_kernel, cudaFuncAttributeMaxDynamicSharedMemorySize, gram_smem);
    cudaFuncSetAttribute(conv_kernel, cudaFuncAttributeMaxDynamicSharedMemorySize, conv_smem);

    gram_kernel<<<dim3(NPAIR, NB), 256, gram_smem>>>(x);
    conv_kernel<<<dim3(NT / 128, NB), 256, conv_smem>>>(x, W, bias, out);
}